// round 1
// baseline (speedup 1.0000x reference)
#include <cuda_runtime.h>
#include <cuda_bf16.h>

#define BATCH 8
#define NT 1024
#define DIM 768
#define NH 12
#define HD 64
#define SCALE 0.125f

// scratch (allocation-free rule: __device__ globals)
__device__ float g_q[BATCH * NH * NT * HD];
__device__ float g_k[BATCH * NH * NT * HD];
__device__ float g_v[BATCH * NH * NT * HD];
__device__ float g_x[BATCH * NT * DIM];

// ---------------------------------------------------------------------------
// Tiled SGEMM: C[m,n] = sum_k A[m,k] * W[n,k] + bias[n]
// A: [M=8192, K=768] row-major, W: [N=768, K=768] row-major.
// BM=BN=64, BK=16, 256 threads, 4x4 microtile.
// ---------------------------------------------------------------------------

__device__ __forceinline__ void gemm_tile_body(
    const float* __restrict__ A, const float* __restrict__ W,
    int m0, int n0, int tid, float acc[4][4],
    float As[16][68], float Bs[16][68])
{
    const int r0 = (tid >> 4) * 4;   // 0..60
    const int c0 = (tid & 15) * 4;   // 0..60

    for (int k0 = 0; k0 < DIM; k0 += 16) {
        // load tiles (transpose to k-major)
        {
            int m  = tid >> 2;          // 0..63
            int kq = (tid & 3) * 4;     // 0,4,8,12
            float4 av = *(const float4*)&A[(size_t)(m0 + m) * DIM + k0 + kq];
            As[kq + 0][m] = av.x; As[kq + 1][m] = av.y;
            As[kq + 2][m] = av.z; As[kq + 3][m] = av.w;
            float4 wv = *(const float4*)&W[(size_t)(n0 + m) * DIM + k0 + kq];
            Bs[kq + 0][m] = wv.x; Bs[kq + 1][m] = wv.y;
            Bs[kq + 2][m] = wv.z; Bs[kq + 3][m] = wv.w;
        }
        __syncthreads();
#pragma unroll
        for (int k = 0; k < 16; ++k) {
            float4 a = *(const float4*)&As[k][r0];
            float4 b = *(const float4*)&Bs[k][c0];
            acc[0][0] += a.x * b.x; acc[0][1] += a.x * b.y; acc[0][2] += a.x * b.z; acc[0][3] += a.x * b.w;
            acc[1][0] += a.y * b.x; acc[1][1] += a.y * b.y; acc[1][2] += a.y * b.z; acc[1][3] += a.y * b.w;
            acc[2][0] += a.z * b.x; acc[2][1] += a.z * b.y; acc[2][2] += a.z * b.z; acc[2][3] += a.z * b.w;
            acc[3][0] += a.w * b.x; acc[3][1] += a.w * b.y; acc[3][2] += a.w * b.z; acc[3][3] += a.w * b.w;
        }
        __syncthreads();
    }
}

// QKV projection: grid (12, 128, 3); z selects q/k/v. Epilogue writes
// [B*H, NT, HD] layout for the attention kernel.
__global__ void qkv_gemm_kernel(
    const float* __restrict__ A,
    const float* __restrict__ Wq, const float* __restrict__ bq,
    const float* __restrict__ Wk, const float* __restrict__ bk,
    const float* __restrict__ Wv, const float* __restrict__ bv)
{
    __shared__ float As[16][68];
    __shared__ float Bs[16][68];

    const float* W; const float* bias; float* out;
    if (blockIdx.z == 0)      { W = Wq; bias = bq; out = g_q; }
    else if (blockIdx.z == 1) { W = Wk; bias = bk; out = g_k; }
    else                      { W = Wv; bias = bv; out = g_v; }

    const int tid = threadIdx.x;
    const int m0 = blockIdx.y * 64;
    const int n0 = blockIdx.x * 64;

    float acc[4][4] = {};
    gemm_tile_body(A, W, m0, n0, tid, acc, As, Bs);

    const int r0 = (tid >> 4) * 4;
    const int c0 = (tid & 15) * 4;
#pragma unroll
    for (int i = 0; i < 4; ++i) {
        int m = m0 + r0 + i;
        int b = m >> 10, t = m & 1023;
#pragma unroll
        for (int j = 0; j < 4; ++j) {
            int n = n0 + c0 + j;
            int h = n >> 6, d = n & 63;
            out[((size_t)(b * NH + h) * NT + t) * HD + d] = acc[i][j] + bias[n];
        }
    }
}

// Output projection: reads g_x [8192, 768], writes d_out x region [8192, 768].
__global__ void proj_gemm_kernel(
    const float* __restrict__ W, const float* __restrict__ bias,
    float* __restrict__ out)
{
    __shared__ float As[16][68];
    __shared__ float Bs[16][68];

    const int tid = threadIdx.x;
    const int m0 = blockIdx.y * 64;
    const int n0 = blockIdx.x * 64;

    float acc[4][4] = {};
    gemm_tile_body(g_x, W, m0, n0, tid, acc, As, Bs);

    const int r0 = (tid >> 4) * 4;
    const int c0 = (tid & 15) * 4;
#pragma unroll
    for (int i = 0; i < 4; ++i) {
        int m = m0 + r0 + i;
#pragma unroll
        for (int j = 0; j < 4; ++j) {
            int n = n0 + c0 + j;
            out[(size_t)m * DIM + n] = acc[i][j] + bias[n];
        }
    }
}

// ---------------------------------------------------------------------------
// Attention: one block per (qtile=32, h, b). 256 threads.
// Scores tile [32][1024] resident in smem -> exact softmax, single attn write.
// ---------------------------------------------------------------------------
__global__ void attn_kernel(float* __restrict__ attn_out, float* __restrict__ xbuf)
{
    extern __shared__ float sm[];
    float* Sc     = sm;                       // [32][1024]
    float* Ks     = Sc + 32 * 1024;           // [64][65]  (also V tile)
    float* Qs     = Ks + 64 * 65;             // [32][65]
    float* rowinv = Qs + 32 * 65;             // [32] (holds sum, then 1/sum)

    const int tid = threadIdx.x;
    const int q0 = blockIdx.x * 32;
    const int h  = blockIdx.y;
    const int b  = blockIdx.z;
    const int bh = b * NH + h;

    const float* Qp = g_q + ((size_t)bh * NT + q0) * HD;
    const float* Kp = g_k + (size_t)bh * NT * HD;
    const float* Vp = g_v + (size_t)bh * NT * HD;

    // load Q tile 32x64 (pad 65)
    for (int idx = tid; idx < 512; idx += 256) {
        int q = idx >> 4, dq = (idx & 15) << 2;
        float4 v = *(const float4*)&Qp[q * HD + dq];
        float* p = &Qs[q * 65 + dq];
        p[0] = v.x; p[1] = v.y; p[2] = v.z; p[3] = v.w;
    }

    const int ty = tid >> 5;   // 0..7 -> q rows ty*4 .. ty*4+3
    const int tx = tid & 31;   // k/d columns tx, tx+32

    // ---- S = Q K^T * SCALE ----
    for (int kt = 0; kt < 16; ++kt) {
        __syncthreads();
        // load K tile 64x64 -> Ks (pad 65)
        for (int idx = tid; idx < 1024; idx += 256) {
            int r = idx >> 4, dq = (idx & 15) << 2;
            float4 v = *(const float4*)&Kp[(size_t)(kt * 64 + r) * HD + dq];
            float* p = &Ks[r * 65 + dq];
            p[0] = v.x; p[1] = v.y; p[2] = v.z; p[3] = v.w;
        }
        __syncthreads();

        float acc[4][2] = {};
#pragma unroll
        for (int d = 0; d < 64; ++d) {
            float k0v = Ks[tx * 65 + d];
            float k1v = Ks[(tx + 32) * 65 + d];
#pragma unroll
            for (int i = 0; i < 4; ++i) {
                float qv = Qs[(ty * 4 + i) * 65 + d];
                acc[i][0] += qv * k0v;
                acc[i][1] += qv * k1v;
            }
        }
#pragma unroll
        for (int i = 0; i < 4; ++i) {
            Sc[(ty * 4 + i) * 1024 + kt * 64 + tx]      = acc[i][0] * SCALE;
            Sc[(ty * 4 + i) * 1024 + kt * 64 + tx + 32] = acc[i][1] * SCALE;
        }
    }
    __syncthreads();

    // ---- softmax (warp per row, 4 rows/warp) ----
    {
        const int warp = tid >> 5, lane = tid & 31;
        for (int r = warp; r < 32; r += 8) {
            float mx = -1e30f;
            for (int j = lane; j < 1024; j += 32) mx = fmaxf(mx, Sc[r * 1024 + j]);
#pragma unroll
            for (int o = 16; o; o >>= 1) mx = fmaxf(mx, __shfl_xor_sync(0xffffffffu, mx, o));
            float s = 0.f;
            for (int j = lane; j < 1024; j += 32) {
                float e = __expf(Sc[r * 1024 + j] - mx);
                Sc[r * 1024 + j] = e;   // unnormalized
                s += e;
            }
#pragma unroll
            for (int o = 16; o; o >>= 1) s += __shfl_xor_sync(0xffffffffu, s, o);
            if (lane == 0) rowinv[r] = s;
        }
    }
    __syncthreads();
    if (tid < 32) rowinv[tid] = 1.0f / rowinv[tid];
    __syncthreads();

    // ---- write normalized attn to global (float4) ----
    {
        float* ap = attn_out + ((size_t)bh * NT + q0) * NT;
        for (int idx = tid; idx < 8192; idx += 256) {
            int r = idx >> 8;
            int c = (idx & 255) << 2;
            float inv = rowinv[r];
            float4 v = *(float4*)&Sc[r * 1024 + c];
            v.x *= inv; v.y *= inv; v.z *= inv; v.w *= inv;
            *(float4*)&ap[(size_t)r * NT + c] = v;
        }
    }

    // ---- O = P V  (unnormalized P; scale by rowinv at the end) ----
    float o[4][2] = {};
    for (int vt = 0; vt < 16; ++vt) {
        __syncthreads();
        for (int idx = tid; idx < 1024; idx += 256) {
            int r = idx >> 4, dq = (idx & 15) << 2;
            float4 v = *(const float4*)&Vp[(size_t)(vt * 64 + r) * HD + dq];
            float* p = &Ks[r * 65 + dq];
            p[0] = v.x; p[1] = v.y; p[2] = v.z; p[3] = v.w;
        }
        __syncthreads();
#pragma unroll
        for (int kk = 0; kk < 64; ++kk) {
            float v0 = Ks[kk * 65 + tx];
            float v1 = Ks[kk * 65 + tx + 32];
#pragma unroll
            for (int i = 0; i < 4; ++i) {
                float p = Sc[(ty * 4 + i) * 1024 + vt * 64 + kk];
                o[i][0] += p * v0;
                o[i][1] += p * v1;
            }
        }
    }

    // epilogue: xbuf[(b*NT + q) * DIM + h*64 + d]
#pragma unroll
    for (int i = 0; i < 4; ++i) {
        int q = q0 + ty * 4 + i;
        float inv = rowinv[ty * 4 + i];
        float* xp = xbuf + ((size_t)b * NT + q) * DIM + h * HD;
        xp[tx]      = o[i][0] * inv;
        xp[tx + 32] = o[i][1] * inv;
    }
}

// ---------------------------------------------------------------------------

extern "C" void kernel_launch(void* const* d_in, const int* in_sizes, int n_in,
                              void* d_out, int out_size)
{
    const float* tfeat = (const float*)d_in[0];
    const float* wq = (const float*)d_in[1];
    const float* bq = (const float*)d_in[2];
    const float* wk = (const float*)d_in[3];
    const float* bk = (const float*)d_in[4];
    const float* wv = (const float*)d_in[5];
    const float* bv = (const float*)d_in[6];
    const float* wp = (const float*)d_in[7];
    const float* bp = (const float*)d_in[8];

    float* xout = (float*)d_out;                                   // [8,1024,768]
    float* attn_out = (float*)d_out + (size_t)BATCH * NT * DIM;    // [8,12,1024,1024]

    float* gx;
    cudaGetSymbolAddress((void**)&gx, g_x);

    // 1) QKV projections
    qkv_gemm_kernel<<<dim3(DIM / 64, (BATCH * NT) / 64, 3), 256>>>(
        tfeat, wq, bq, wk, bk, wv, bv);

    // 2) fused attention + attn write + per-head output into g_x
    const int smem_bytes = (32 * 1024 + 64 * 65 + 32 * 65 + 32) * (int)sizeof(float);
    cudaFuncSetAttribute(attn_kernel, cudaFuncAttributeMaxDynamicSharedMemorySize, smem_bytes);
    attn_kernel<<<dim3(NT / 32, NH, BATCH), 256, smem_bytes>>>(attn_out, gx);

    // 3) output projection
    proj_gemm_kernel<<<dim3(DIM / 64, (BATCH * NT) / 64), 256>>>(wp, bp, xout);
}

// round 2
// speedup vs baseline: 1.8950x; 1.8950x over previous
#include <cuda_runtime.h>
#include <cuda_bf16.h>

#define BATCH 8
#define NT 1024
#define DIM 768
#define NH 12
#define HD 64
#define SCALE 0.125f
#define NBH (BATCH * NH)

// scratch (allocation-free rule: __device__ globals)
__device__ float g_q[NBH * NT * HD];
__device__ float g_k[NBH * NT * HD];
__device__ float g_v[NBH * NT * HD];
__device__ float g_x[BATCH * NT * DIM];
__device__ float g_psum[(size_t)NBH * NT * 8];   // per-(row, col-block) exp sums

// ---------------------------------------------------------------------------
// Shared 128x128x16-step GEMM core: C[m,n] = sum_k A[m,k] * B[n,k]
// 256 threads, 8x8 microtile. As/Bs stored k-major [16][132].
// ---------------------------------------------------------------------------

__device__ __forceinline__ void load_tile16(const float* __restrict__ P, int ld,
                                            int row_base, int k0, int tid,
                                            float S[16][132])
{
#pragma unroll
    for (int u = 0; u < 2; ++u) {
        int idx = tid + u * 256;       // 0..511
        int row = idx >> 2;            // 0..127
        int kq  = (idx & 3) << 2;      // 0,4,8,12
        float4 v = *(const float4*)&P[(size_t)(row_base + row) * ld + k0 + kq];
        S[kq + 0][row] = v.x; S[kq + 1][row] = v.y;
        S[kq + 2][row] = v.z; S[kq + 3][row] = v.w;
    }
}

__device__ __forceinline__ void gemm_acc(const float* __restrict__ A,
                                         const float* __restrict__ B,
                                         int lda, int ldb, int K,
                                         int m0, int n0, int tid,
                                         float acc[8][8],
                                         float As[16][132], float Bs[16][132])
{
    const int tx4 = (tid & 15) << 2;
    const int ty4 = (tid >> 4) << 2;

    for (int k0 = 0; k0 < K; k0 += 16) {
        load_tile16(A, lda, m0, k0, tid, As);
        load_tile16(B, ldb, n0, k0, tid, Bs);
        __syncthreads();
#pragma unroll
        for (int k = 0; k < 16; ++k) {
            float4 a0 = *(const float4*)&As[k][ty4];
            float4 a1 = *(const float4*)&As[k][ty4 + 64];
            float4 b0 = *(const float4*)&Bs[k][tx4];
            float4 b1 = *(const float4*)&Bs[k][tx4 + 64];
            float av[8] = {a0.x, a0.y, a0.z, a0.w, a1.x, a1.y, a1.z, a1.w};
            float bv[8] = {b0.x, b0.y, b0.z, b0.w, b1.x, b1.y, b1.z, b1.w};
#pragma unroll
            for (int i = 0; i < 8; ++i)
#pragma unroll
                for (int j = 0; j < 8; ++j)
                    acc[i][j] += av[i] * bv[j];
        }
        __syncthreads();
    }
}

// row/col index of microtile element i (0..7): lo quad at ty4+i, hi quad at 64+ty4+(i-4)
#define MT_IDX(base4, i) (((i & 4) << 4) + (base4) + ((i) & 3))

// ---------------------------------------------------------------------------
// 1) QKV projection. grid (6, 64, 3). Epilogue -> [B*H, NT, HD].
// ---------------------------------------------------------------------------
__global__ __launch_bounds__(256, 2) void qkv_gemm_kernel(
    const float* __restrict__ A,
    const float* __restrict__ Wq, const float* __restrict__ bq,
    const float* __restrict__ Wk, const float* __restrict__ bk,
    const float* __restrict__ Wv, const float* __restrict__ bv)
{
    __shared__ float As[16][132];
    __shared__ float Bs[16][132];

    const float* W; const float* bias; float* out;
    if (blockIdx.z == 0)      { W = Wq; bias = bq; out = g_q; }
    else if (blockIdx.z == 1) { W = Wk; bias = bk; out = g_k; }
    else                      { W = Wv; bias = bv; out = g_v; }

    const int tid = threadIdx.x;
    const int m0 = blockIdx.y * 128;
    const int n0 = blockIdx.x * 128;
    const int tx4 = (tid & 15) << 2;
    const int ty4 = (tid >> 4) << 2;

    float acc[8][8] = {};
    gemm_acc(A, W, DIM, DIM, DIM, m0, n0, tid, acc, As, Bs);

    const float4 b_lo = *(const float4*)&bias[n0 + tx4];
    const float4 b_hi = *(const float4*)&bias[n0 + 64 + tx4];
    const int h_lo = (n0 + tx4) >> 6;
    const int h_hi = (n0 + 64 + tx4) >> 6;
    const int d_lo = tx4 & 63;   // n0 is a multiple of 128 -> d = tx4

#pragma unroll
    for (int i = 0; i < 8; ++i) {
        int m = m0 + MT_IDX(ty4, i);
        int b = m >> 10, t = m & 1023;
        float4 lo = make_float4(acc[i][0] + b_lo.x, acc[i][1] + b_lo.y,
                                acc[i][2] + b_lo.z, acc[i][3] + b_lo.w);
        float4 hi = make_float4(acc[i][4] + b_hi.x, acc[i][5] + b_hi.y,
                                acc[i][6] + b_hi.z, acc[i][7] + b_hi.w);
        *(float4*)&out[((size_t)(b * NH + h_lo) * NT + t) * HD + d_lo] = lo;
        *(float4*)&out[((size_t)(b * NH + h_hi) * NT + t) * HD + d_lo] = hi;
    }
}

// ---------------------------------------------------------------------------
// 2) S = exp(Q K^T * SCALE) (unnormalized) -> attn buffer; row-sum partials.
//    grid (8 colblk, 8 rowblk, 96 bh)
// ---------------------------------------------------------------------------
__global__ __launch_bounds__(256, 2) void s_exp_kernel(float* __restrict__ attn)
{
    __shared__ float As[16][132];
    __shared__ float Bs[16][132];

    const int tid = threadIdx.x;
    const int bh = blockIdx.z;
    const int m0 = blockIdx.y * 128;
    const int n0 = blockIdx.x * 128;
    const int tx4 = (tid & 15) << 2;
    const int ty4 = (tid >> 4) << 2;

    const float* Q = g_q + (size_t)bh * NT * HD;
    const float* K = g_k + (size_t)bh * NT * HD;

    float acc[8][8] = {};
    gemm_acc(Q, K, HD, HD, HD, m0, n0, tid, acc, As, Bs);

    float rowpart[8];
#pragma unroll
    for (int i = 0; i < 8; ++i) {
        int m = m0 + MT_IDX(ty4, i);
        float4 e0, e1;
        e0.x = __expf(acc[i][0] * SCALE); e0.y = __expf(acc[i][1] * SCALE);
        e0.z = __expf(acc[i][2] * SCALE); e0.w = __expf(acc[i][3] * SCALE);
        e1.x = __expf(acc[i][4] * SCALE); e1.y = __expf(acc[i][5] * SCALE);
        e1.z = __expf(acc[i][6] * SCALE); e1.w = __expf(acc[i][7] * SCALE);
        float* ap = attn + ((size_t)bh * NT + m) * NT;
        *(float4*)&ap[n0 + tx4] = e0;
        *(float4*)&ap[n0 + 64 + tx4] = e1;
        rowpart[i] = e0.x + e0.y + e0.z + e0.w + e1.x + e1.y + e1.z + e1.w;
    }
    // reduce over the 16 threads (tx) that share each row group
#pragma unroll
    for (int off = 1; off < 16; off <<= 1)
#pragma unroll
        for (int i = 0; i < 8; ++i)
            rowpart[i] += __shfl_xor_sync(0xffffffffu, rowpart[i], off);

    if ((tid & 15) == 0) {
#pragma unroll
        for (int i = 0; i < 8; ++i) {
            int m = m0 + MT_IDX(ty4, i);
            g_psum[((size_t)bh * NT + m) * 8 + blockIdx.x] = rowpart[i];
        }
    }
}

// ---------------------------------------------------------------------------
// 3) O = P V with in-place normalization of P (final attn write happens here).
//    grid (8 rowblk, 96 bh). BM=128, BN=64, BK=32, 8x4 microtile.
// ---------------------------------------------------------------------------
__global__ __launch_bounds__(256, 2) void pv_kernel(float* __restrict__ attn)
{
    __shared__ float Ps[32][132];
    __shared__ float Vs[32][68];
    __shared__ float invs[128];

    const int tid = threadIdx.x;
    const int m0 = blockIdx.x * 128;
    const int bh = blockIdx.y;
    const int tx4 = (tid & 15) << 2;
    const int ty4 = (tid >> 4) << 2;

    for (int r = tid; r < 128; r += 256) {
        const float* pp = &g_psum[((size_t)bh * NT + m0 + r) * 8];
        float s = pp[0] + pp[1] + pp[2] + pp[3] + pp[4] + pp[5] + pp[6] + pp[7];
        invs[r] = 1.0f / s;
    }
    __syncthreads();

    float* Pg = attn + (size_t)bh * NT * NT;
    const float* V = g_v + (size_t)bh * NT * HD;

    float acc[8][4] = {};
    for (int k0 = 0; k0 < NT; k0 += 32) {
        // load P tile, normalize, write back final attn, stage k-major
#pragma unroll
        for (int u = 0; u < 4; ++u) {
            int idx = tid + u * 256;      // 0..1023
            int row = idx >> 3;           // 0..127
            int kq  = (idx & 7) << 2;     // 0..28
            float* gp = Pg + (size_t)(m0 + row) * NT + k0 + kq;
            float4 v = *(float4*)gp;
            float iv = invs[row];
            v.x *= iv; v.y *= iv; v.z *= iv; v.w *= iv;
            *(float4*)gp = v;
            Ps[kq + 0][row] = v.x; Ps[kq + 1][row] = v.y;
            Ps[kq + 2][row] = v.z; Ps[kq + 3][row] = v.w;
        }
        // load V tile (already k-major)
#pragma unroll
        for (int u = 0; u < 2; ++u) {
            int idx = tid + u * 256;      // 0..511
            int kk = idx >> 4;            // 0..31
            int dq = (idx & 15) << 2;
            *(float4*)&Vs[kk][dq] = *(const float4*)&V[(size_t)(k0 + kk) * HD + dq];
        }
        __syncthreads();
#pragma unroll
        for (int k = 0; k < 32; ++k) {
            float4 a0 = *(const float4*)&Ps[k][ty4];
            float4 a1 = *(const float4*)&Ps[k][ty4 + 64];
            float4 bv = *(const float4*)&Vs[k][tx4];
            float av[8] = {a0.x, a0.y, a0.z, a0.w, a1.x, a1.y, a1.z, a1.w};
#pragma unroll
            for (int i = 0; i < 8; ++i) {
                acc[i][0] += av[i] * bv.x;
                acc[i][1] += av[i] * bv.y;
                acc[i][2] += av[i] * bv.z;
                acc[i][3] += av[i] * bv.w;
            }
        }
        __syncthreads();
    }

    const int b = bh / NH, h = bh % NH;
#pragma unroll
    for (int i = 0; i < 8; ++i) {
        int m = m0 + MT_IDX(ty4, i);
        float4 o = make_float4(acc[i][0], acc[i][1], acc[i][2], acc[i][3]);
        *(float4*)&g_x[((size_t)b * NT + m) * DIM + h * HD + tx4] = o;
    }
}

// ---------------------------------------------------------------------------
// 4) output projection: x = g_x @ wp^T + bp
// ---------------------------------------------------------------------------
__global__ __launch_bounds__(256, 2) void proj_gemm_kernel(
    const float* __restrict__ W, const float* __restrict__ bias,
    float* __restrict__ out)
{
    __shared__ float As[16][132];
    __shared__ float Bs[16][132];

    const int tid = threadIdx.x;
    const int m0 = blockIdx.y * 128;
    const int n0 = blockIdx.x * 128;
    const int tx4 = (tid & 15) << 2;
    const int ty4 = (tid >> 4) << 2;

    float acc[8][8] = {};
    gemm_acc(g_x, W, DIM, DIM, DIM, m0, n0, tid, acc, As, Bs);

    const float4 b_lo = *(const float4*)&bias[n0 + tx4];
    const float4 b_hi = *(const float4*)&bias[n0 + 64 + tx4];

#pragma unroll
    for (int i = 0; i < 8; ++i) {
        int m = m0 + MT_IDX(ty4, i);
        float4 lo = make_float4(acc[i][0] + b_lo.x, acc[i][1] + b_lo.y,
                                acc[i][2] + b_lo.z, acc[i][3] + b_lo.w);
        float4 hi = make_float4(acc[i][4] + b_hi.x, acc[i][5] + b_hi.y,
                                acc[i][6] + b_hi.z, acc[i][7] + b_hi.w);
        *(float4*)&out[(size_t)m * DIM + n0 + tx4] = lo;
        *(float4*)&out[(size_t)m * DIM + n0 + 64 + tx4] = hi;
    }
}

// ---------------------------------------------------------------------------

extern "C" void kernel_launch(void* const* d_in, const int* in_sizes, int n_in,
                              void* d_out, int out_size)
{
    const float* tfeat = (const float*)d_in[0];
    const float* wq = (const float*)d_in[1];
    const float* bq = (const float*)d_in[2];
    const float* wk = (const float*)d_in[3];
    const float* bk = (const float*)d_in[4];
    const float* wv = (const float*)d_in[5];
    const float* bv = (const float*)d_in[6];
    const float* wp = (const float*)d_in[7];
    const float* bp = (const float*)d_in[8];

    float* xout = (float*)d_out;                                   // [8,1024,768]
    float* attn_out = (float*)d_out + (size_t)BATCH * NT * DIM;    // [8,12,1024,1024]

    // 1) QKV projections
    qkv_gemm_kernel<<<dim3(DIM / 128, (BATCH * NT) / 128, 3), 256>>>(
        tfeat, wq, bq, wk, bk, wv, bv);

    // 2) unnormalized exp scores + row-sum partials
    s_exp_kernel<<<dim3(NT / 128, NT / 128, NBH), 256>>>(attn_out);

    // 3) PV gemm + in-place attn normalization
    pv_kernel<<<dim3(NT / 128, NBH), 256>>>(attn_out);

    // 4) output projection
    proj_gemm_kernel<<<dim3(DIM / 128, (BATCH * NT) / 128), 256>>>(wp, bp, xout);
}

// round 3
// speedup vs baseline: 3.7113x; 1.9585x over previous
#include <cuda_runtime.h>
#include <cuda_bf16.h>
#include <cstdint>

#define BATCH 8
#define NT 1024
#define DIM 768
#define NH 12
#define HD 64
#define SCALE 0.125f
#define NBH (BATCH * NH)

// scratch (allocation-free rule: __device__ globals)
__device__ float g_q[NBH * NT * HD];
__device__ float g_k[NBH * NT * HD];
__device__ float g_v[NBH * NT * HD];
__device__ float g_x[BATCH * NT * DIM];
__device__ float g_psum[(size_t)NBH * NT * 8];

// ---------------------------------------------------------------------------
// TF32 mma helpers
// ---------------------------------------------------------------------------
__device__ __forceinline__ uint32_t f2tf(float x) {
    uint32_t r;
    asm("cvt.rna.tf32.f32 %0, %1;" : "=r"(r) : "f"(x));
    return r;
}

__device__ __forceinline__ void mma8(float* c,
                                     uint32_t a0, uint32_t a1, uint32_t a2, uint32_t a3,
                                     uint32_t b0, uint32_t b1) {
    asm volatile(
        "mma.sync.aligned.m16n8k8.row.col.f32.tf32.tf32.f32 "
        "{%0,%1,%2,%3},{%4,%5,%6,%7},{%8,%9},{%0,%1,%2,%3};"
        : "+f"(c[0]), "+f"(c[1]), "+f"(c[2]), "+f"(c[3])
        : "r"(a0), "r"(a1), "r"(a2), "r"(a3), "r"(b0), "r"(b1));
}

// load a 128x32 fp32 tile -> tf32 smem [row][36] (row-major, padded)
__device__ __forceinline__ void load_tile_tf32(const float* __restrict__ P, int ld,
                                               int row0, int k0, int tid,
                                               uint32_t* __restrict__ S) {
#pragma unroll
    for (int u = 0; u < 4; ++u) {
        int idx = tid + u * 256;
        int row = idx >> 3;
        int kq = (idx & 7) << 2;
        float4 v = *(const float4*)&P[(size_t)(row0 + row) * ld + k0 + kq];
        uint4 t;
        t.x = f2tf(v.x); t.y = f2tf(v.y); t.z = f2tf(v.z); t.w = f2tf(v.w);
        *(uint4*)&S[row * 36 + kq] = t;
    }
}

// one 32-deep K-tile of a 128x128 block: 8 warps as 2x4, warp tile 64x32
__device__ __forceinline__ void compute_ktile128(const uint32_t* __restrict__ As,
                                                 const uint32_t* __restrict__ Bs,
                                                 int wm, int wn, int lane,
                                                 float acc[4][4][4]) {
#pragma unroll
    for (int ks = 0; ks < 4; ++ks) {
        const int col = ks * 8 + (lane & 3);
        uint32_t a[4][4], b[4][2];
#pragma unroll
        for (int mt = 0; mt < 4; ++mt) {
            int r = wm * 64 + mt * 16 + (lane >> 2);
            a[mt][0] = As[r * 36 + col];
            a[mt][1] = As[(r + 8) * 36 + col];
            a[mt][2] = As[r * 36 + col + 4];
            a[mt][3] = As[(r + 8) * 36 + col + 4];
        }
#pragma unroll
        for (int nt = 0; nt < 4; ++nt) {
            int n = wn * 32 + nt * 8 + (lane >> 2);
            b[nt][0] = Bs[n * 36 + col];
            b[nt][1] = Bs[n * 36 + col + 4];
        }
#pragma unroll
        for (int mt = 0; mt < 4; ++mt)
#pragma unroll
            for (int nt = 0; nt < 4; ++nt)
                mma8(acc[mt][nt], a[mt][0], a[mt][1], a[mt][2], a[mt][3],
                     b[nt][0], b[nt][1]);
    }
}

// ---------------------------------------------------------------------------
// 1) QKV projection. grid (6, 64, 3). C = A @ W^T + b -> [B*H, NT, HD]
// ---------------------------------------------------------------------------
__global__ __launch_bounds__(256, 2) void qkv_gemm_kernel(
    const float* __restrict__ A,
    const float* __restrict__ Wq, const float* __restrict__ bq,
    const float* __restrict__ Wk, const float* __restrict__ bk,
    const float* __restrict__ Wv, const float* __restrict__ bv)
{
    __shared__ uint32_t As[128 * 36];
    __shared__ uint32_t Bs[128 * 36];

    const float* W; const float* bias; float* out;
    if (blockIdx.z == 0)      { W = Wq; bias = bq; out = g_q; }
    else if (blockIdx.z == 1) { W = Wk; bias = bk; out = g_k; }
    else                      { W = Wv; bias = bv; out = g_v; }

    const int tid = threadIdx.x;
    const int lane = tid & 31;
    const int wid = tid >> 5;
    const int wm = wid >> 2, wn = wid & 3;
    const int m0 = blockIdx.y * 128;
    const int n0 = blockIdx.x * 128;

    float acc[4][4][4] = {};
    for (int k0 = 0; k0 < DIM; k0 += 32) {
        load_tile_tf32(A, DIM, m0, k0, tid, As);
        load_tile_tf32(W, DIM, n0, k0, tid, Bs);
        __syncthreads();
        compute_ktile128(As, Bs, wm, wn, lane, acc);
        __syncthreads();
    }

#pragma unroll
    for (int mt = 0; mt < 4; ++mt) {
        int row = m0 + wm * 64 + mt * 16 + (lane >> 2);
        int b0i = row >> 10, t0 = row & 1023;
#pragma unroll
        for (int nt = 0; nt < 4; ++nt) {
            int col = n0 + wn * 32 + nt * 8 + ((lane & 3) << 1);
            int h = col >> 6, d = col & 63;
            float bx = bias[col], by = bias[col + 1];
            float2 lo = make_float2(acc[mt][nt][0] + bx, acc[mt][nt][1] + by);
            float2 hi = make_float2(acc[mt][nt][2] + bx, acc[mt][nt][3] + by);
            *(float2*)&out[((size_t)(b0i * NH + h) * NT + t0) * HD + d] = lo;
            *(float2*)&out[((size_t)(b0i * NH + h) * NT + t0 + 8) * HD + d] = hi;
        }
    }
}

// ---------------------------------------------------------------------------
// 2) S = exp(Q K^T * SCALE) (unnormalized) + row-sum partials.
//    grid (8 colblk, 8 rowblk, 96)
// ---------------------------------------------------------------------------
__global__ __launch_bounds__(256, 2) void s_exp_kernel(float* __restrict__ attn)
{
    __shared__ uint32_t As[128 * 36];
    __shared__ uint32_t Bs[128 * 36];
    __shared__ float redsum[4][128];

    const int tid = threadIdx.x;
    const int lane = tid & 31;
    const int wid = tid >> 5;
    const int wm = wid >> 2, wn = wid & 3;
    const int bh = blockIdx.z;
    const int m0 = blockIdx.y * 128;
    const int n0 = blockIdx.x * 128;

    const float* Q = g_q + (size_t)bh * NT * HD;
    const float* K = g_k + (size_t)bh * NT * HD;

    float acc[4][4][4] = {};
#pragma unroll
    for (int k0 = 0; k0 < HD; k0 += 32) {
        load_tile_tf32(Q, HD, m0, k0, tid, As);
        load_tile_tf32(K, HD, n0, k0, tid, Bs);
        __syncthreads();
        compute_ktile128(As, Bs, wm, wn, lane, acc);
        __syncthreads();
    }

    float rsum[4][2] = {};
    float* ap = attn + (size_t)bh * NT * NT;
#pragma unroll
    for (int mt = 0; mt < 4; ++mt) {
        int row = m0 + wm * 64 + mt * 16 + (lane >> 2);
#pragma unroll
        for (int nt = 0; nt < 4; ++nt) {
            int col = n0 + wn * 32 + nt * 8 + ((lane & 3) << 1);
            float e0 = __expf(acc[mt][nt][0] * SCALE);
            float e1 = __expf(acc[mt][nt][1] * SCALE);
            float e2 = __expf(acc[mt][nt][2] * SCALE);
            float e3 = __expf(acc[mt][nt][3] * SCALE);
            *(float2*)&ap[(size_t)row * NT + col] = make_float2(e0, e1);
            *(float2*)&ap[(size_t)(row + 8) * NT + col] = make_float2(e2, e3);
            rsum[mt][0] += e0 + e1;
            rsum[mt][1] += e2 + e3;
        }
    }
#pragma unroll
    for (int off = 1; off < 4; off <<= 1)
#pragma unroll
        for (int mt = 0; mt < 4; ++mt) {
            rsum[mt][0] += __shfl_xor_sync(0xffffffffu, rsum[mt][0], off);
            rsum[mt][1] += __shfl_xor_sync(0xffffffffu, rsum[mt][1], off);
        }
    if ((lane & 3) == 0) {
#pragma unroll
        for (int mt = 0; mt < 4; ++mt) {
            int r = wm * 64 + mt * 16 + (lane >> 2);
            redsum[wn][r] = rsum[mt][0];
            redsum[wn][r + 8] = rsum[mt][1];
        }
    }
    __syncthreads();
    if (tid < 128) {
        float s = redsum[0][tid] + redsum[1][tid] + redsum[2][tid] + redsum[3][tid];
        g_psum[((size_t)bh * NT + m0 + tid) * 8 + blockIdx.x] = s;
    }
}

// ---------------------------------------------------------------------------
// 3) O = P V, normalizing P in place (final attn). grid (8, 96).
//    Block 128x64, warps 4x2, warp tile 32x32.
// ---------------------------------------------------------------------------
__global__ __launch_bounds__(256, 2) void pv_kernel(float* __restrict__ attn)
{
    __shared__ uint32_t Ps[128 * 36];
    __shared__ uint32_t Vs[64 * 36];
    __shared__ float invs[128];

    const int tid = threadIdx.x;
    const int lane = tid & 31;
    const int wid = tid >> 5;
    const int wm = wid >> 1, wn = wid & 1;
    const int m0 = blockIdx.x * 128;
    const int bh = blockIdx.y;

    for (int r = tid; r < 128; r += 256) {
        const float* pp = &g_psum[((size_t)bh * NT + m0 + r) * 8];
        invs[r] = 1.0f / (pp[0] + pp[1] + pp[2] + pp[3] + pp[4] + pp[5] + pp[6] + pp[7]);
    }
    __syncthreads();

    float* Pg = attn + (size_t)bh * NT * NT;
    const float* V = g_v + (size_t)bh * NT * HD;

    float acc[2][4][4] = {};
    for (int k0 = 0; k0 < NT; k0 += 32) {
        // P tile: normalize, write back, stage tf32
#pragma unroll
        for (int u = 0; u < 4; ++u) {
            int idx = tid + u * 256;
            int row = idx >> 3;
            int kq = (idx & 7) << 2;
            float* gp = Pg + (size_t)(m0 + row) * NT + k0 + kq;
            float4 v = *(float4*)gp;
            float iv = invs[row];
            v.x *= iv; v.y *= iv; v.z *= iv; v.w *= iv;
            *(float4*)gp = v;
            uint4 t;
            t.x = f2tf(v.x); t.y = f2tf(v.y); t.z = f2tf(v.z); t.w = f2tf(v.w);
            *(uint4*)&Ps[row * 36 + kq] = t;
        }
        // V tile 32x64 -> Vs[n][36] (n-major)
#pragma unroll
        for (int u = 0; u < 2; ++u) {
            int idx = tid + u * 256;
            int k = idx >> 4;
            int dq = (idx & 15) << 2;
            float4 v = *(const float4*)&V[(size_t)(k0 + k) * HD + dq];
            Vs[(dq + 0) * 36 + k] = f2tf(v.x);
            Vs[(dq + 1) * 36 + k] = f2tf(v.y);
            Vs[(dq + 2) * 36 + k] = f2tf(v.z);
            Vs[(dq + 3) * 36 + k] = f2tf(v.w);
        }
        __syncthreads();
#pragma unroll
        for (int ks = 0; ks < 4; ++ks) {
            const int col = ks * 8 + (lane & 3);
            uint32_t a[2][4], b[4][2];
#pragma unroll
            for (int mt = 0; mt < 2; ++mt) {
                int r = wm * 32 + mt * 16 + (lane >> 2);
                a[mt][0] = Ps[r * 36 + col];
                a[mt][1] = Ps[(r + 8) * 36 + col];
                a[mt][2] = Ps[r * 36 + col + 4];
                a[mt][3] = Ps[(r + 8) * 36 + col + 4];
            }
#pragma unroll
            for (int nt = 0; nt < 4; ++nt) {
                int n = wn * 32 + nt * 8 + (lane >> 2);
                b[nt][0] = Vs[n * 36 + col];
                b[nt][1] = Vs[n * 36 + col + 4];
            }
#pragma unroll
            for (int mt = 0; mt < 2; ++mt)
#pragma unroll
                for (int nt = 0; nt < 4; ++nt)
                    mma8(acc[mt][nt], a[mt][0], a[mt][1], a[mt][2], a[mt][3],
                         b[nt][0], b[nt][1]);
        }
        __syncthreads();
    }

    const int b = bh / NH, h = bh % NH;
#pragma unroll
    for (int mt = 0; mt < 2; ++mt) {
        int row = m0 + wm * 32 + mt * 16 + (lane >> 2);
#pragma unroll
        for (int nt = 0; nt < 4; ++nt) {
            int d = wn * 32 + nt * 8 + ((lane & 3) << 1);
            *(float2*)&g_x[((size_t)b * NT + row) * DIM + h * HD + d] =
                make_float2(acc[mt][nt][0], acc[mt][nt][1]);
            *(float2*)&g_x[((size_t)b * NT + row + 8) * DIM + h * HD + d] =
                make_float2(acc[mt][nt][2], acc[mt][nt][3]);
        }
    }
}

// ---------------------------------------------------------------------------
// 4) output projection: x = g_x @ wp^T + bp. grid (6, 64).
// ---------------------------------------------------------------------------
__global__ __launch_bounds__(256, 2) void proj_gemm_kernel(
    const float* __restrict__ W, const float* __restrict__ bias,
    float* __restrict__ out)
{
    __shared__ uint32_t As[128 * 36];
    __shared__ uint32_t Bs[128 * 36];

    const int tid = threadIdx.x;
    const int lane = tid & 31;
    const int wid = tid >> 5;
    const int wm = wid >> 2, wn = wid & 3;
    const int m0 = blockIdx.y * 128;
    const int n0 = blockIdx.x * 128;

    float acc[4][4][4] = {};
    for (int k0 = 0; k0 < DIM; k0 += 32) {
        load_tile_tf32(g_x, DIM, m0, k0, tid, As);
        load_tile_tf32(W, DIM, n0, k0, tid, Bs);
        __syncthreads();
        compute_ktile128(As, Bs, wm, wn, lane, acc);
        __syncthreads();
    }

#pragma unroll
    for (int mt = 0; mt < 4; ++mt) {
        int row = m0 + wm * 64 + mt * 16 + (lane >> 2);
#pragma unroll
        for (int nt = 0; nt < 4; ++nt) {
            int col = n0 + wn * 32 + nt * 8 + ((lane & 3) << 1);
            float bx = bias[col], by = bias[col + 1];
            *(float2*)&out[(size_t)row * DIM + col] =
                make_float2(acc[mt][nt][0] + bx, acc[mt][nt][1] + by);
            *(float2*)&out[(size_t)(row + 8) * DIM + col] =
                make_float2(acc[mt][nt][2] + bx, acc[mt][nt][3] + by);
        }
    }
}

// ---------------------------------------------------------------------------

extern "C" void kernel_launch(void* const* d_in, const int* in_sizes, int n_in,
                              void* d_out, int out_size)
{
    const float* tfeat = (const float*)d_in[0];
    const float* wq = (const float*)d_in[1];
    const float* bq = (const float*)d_in[2];
    const float* wk = (const float*)d_in[3];
    const float* bk = (const float*)d_in[4];
    const float* wv = (const float*)d_in[5];
    const float* bv = (const float*)d_in[6];
    const float* wp = (const float*)d_in[7];
    const float* bp = (const float*)d_in[8];

    float* xout = (float*)d_out;                                   // [8,1024,768]
    float* attn_out = (float*)d_out + (size_t)BATCH * NT * DIM;    // [8,12,1024,1024]

    qkv_gemm_kernel<<<dim3(DIM / 128, (BATCH * NT) / 128, 3), 256>>>(
        tfeat, wq, bq, wk, bk, wv, bv);

    s_exp_kernel<<<dim3(NT / 128, NT / 128, NBH), 256>>>(attn_out);

    pv_kernel<<<dim3(NT / 128, NBH), 256>>>(attn_out);

    proj_gemm_kernel<<<dim3(DIM / 128, (BATCH * NT) / 128), 256>>>(wp, bp, xout);
}

// round 4
// speedup vs baseline: 5.1905x; 1.3986x over previous
#include <cuda_runtime.h>
#include <cstdint>

#define BATCH 8
#define NT 1024
#define DIM 768
#define NH 12
#define HD 64
#define SCALE 0.125f
#define NBH (BATCH * NH)

// scratch (allocation-free rule: __device__ globals)
__device__ float g_q[NBH * NT * HD];
__device__ float g_k[NBH * NT * HD];
__device__ float g_v[NBH * NT * HD];
__device__ float g_x[BATCH * NT * DIM];
__device__ float g_tf[BATCH * NT * DIM];          // tf32-rounded tfeat
__device__ float g_w[4 * DIM * DIM];              // tf32-rounded wq,wk,wv,wp
__device__ float g_psum[(size_t)NBH * NT * 8];

// ---------------------------------------------------------------------------
// helpers
// ---------------------------------------------------------------------------
__device__ __forceinline__ uint32_t f2tf(float x) {
    uint32_t r;
    asm("cvt.rna.tf32.f32 %0, %1;" : "=r"(r) : "f"(x));
    return r;
}
__device__ __forceinline__ float round_tf(float x) { return __uint_as_float(f2tf(x)); }

__device__ __forceinline__ void cp16(uint32_t s, const void* g) {
    asm volatile("cp.async.cg.shared.global [%0], [%1], 16;" :: "r"(s), "l"(g));
}
__device__ __forceinline__ void cp4(uint32_t s, const void* g) {
    asm volatile("cp.async.ca.shared.global [%0], [%1], 4;" :: "r"(s), "l"(g));
}
__device__ __forceinline__ void cp_commit() { asm volatile("cp.async.commit_group;"); }
template <int N> __device__ __forceinline__ void cp_wait() {
    asm volatile("cp.async.wait_group %0;" :: "n"(N));
}

__device__ __forceinline__ void mma8(float* c,
                                     uint32_t a0, uint32_t a1, uint32_t a2, uint32_t a3,
                                     uint32_t b0, uint32_t b1) {
    asm volatile(
        "mma.sync.aligned.m16n8k8.row.col.f32.tf32.tf32.f32 "
        "{%0,%1,%2,%3},{%4,%5,%6,%7},{%8,%9},{%0,%1,%2,%3};"
        : "+f"(c[0]), "+f"(c[1]), "+f"(c[2]), "+f"(c[3])
        : "r"(a0), "r"(a1), "r"(a2), "r"(a3), "r"(b0), "r"(b1));
}

// 128x128 block, 8 warps as 2x4 (warp tile 64x32), operands at stride STRIDE
template <int STRIDE, int NKS>
__device__ __forceinline__ void compute_tiles(const uint32_t* __restrict__ As,
                                              const uint32_t* __restrict__ Bs,
                                              int wm, int wn, int lane,
                                              float acc[4][4][4]) {
#pragma unroll
    for (int ks = 0; ks < NKS; ++ks) {
        const int col = ks * 8 + (lane & 3);
        uint32_t a[4][4], b[4][2];
#pragma unroll
        for (int mt = 0; mt < 4; ++mt) {
            int r = wm * 64 + mt * 16 + (lane >> 2);
            a[mt][0] = As[r * STRIDE + col];
            a[mt][1] = As[(r + 8) * STRIDE + col];
            a[mt][2] = As[r * STRIDE + col + 4];
            a[mt][3] = As[(r + 8) * STRIDE + col + 4];
        }
#pragma unroll
        for (int nt = 0; nt < 4; ++nt) {
            int n = wn * 32 + nt * 8 + (lane >> 2);
            b[nt][0] = Bs[n * STRIDE + col];
            b[nt][1] = Bs[n * STRIDE + col + 4];
        }
#pragma unroll
        for (int mt = 0; mt < 4; ++mt)
#pragma unroll
            for (int nt = 0; nt < 4; ++nt)
                mma8(acc[mt][nt], a[mt][0], a[mt][1], a[mt][2], a[mt][3],
                     b[nt][0], b[nt][1]);
    }
}

// ---------------------------------------------------------------------------
// 0) tf32 pre-rounding
// ---------------------------------------------------------------------------
__global__ void round_kernel(const float* __restrict__ src, float* __restrict__ dst, int n4) {
    int i = blockIdx.x * blockDim.x + threadIdx.x;
    if (i < n4) {
        float4 v = ((const float4*)src)[i];
        v.x = round_tf(v.x); v.y = round_tf(v.y);
        v.z = round_tf(v.z); v.w = round_tf(v.w);
        ((float4*)dst)[i] = v;
    }
}

// ---------------------------------------------------------------------------
// 1) QKV projection, cp.async double-buffered. grid (6, 64, 3).
// smem: As0,As1,Bs0,Bs1 each 128*36 u32 -> 73728 B dynamic.
// ---------------------------------------------------------------------------
__global__ __launch_bounds__(256, 2) void qkv_gemm_kernel(
    const float* __restrict__ bq, const float* __restrict__ bk,
    const float* __restrict__ bv)
{
    extern __shared__ uint32_t sm[];
    const uint32_t sbase = (uint32_t)__cvta_generic_to_shared(sm);

    const int z = blockIdx.z;
    const float* A = g_tf;
    const float* W = g_w + (size_t)z * DIM * DIM;
    const float* bias = (z == 0) ? bq : (z == 1) ? bk : bv;
    float* out = (z == 0) ? g_q : (z == 1) ? g_k : g_v;

    const int tid = threadIdx.x;
    const int lane = tid & 31;
    const int wid = tid >> 5;
    const int wm = wid >> 2, wn = wid & 3;
    const int m0 = blockIdx.y * 128;
    const int n0 = blockIdx.x * 128;

    const int srow = tid >> 3;
    const int skq = (tid & 7) << 2;

    auto stage = [&](int buf, int k0) {
        uint32_t aofs = sbase + (uint32_t)(buf * 4608) * 4;
        uint32_t bofs = sbase + (uint32_t)(9216 + buf * 4608) * 4;
#pragma unroll
        for (int u = 0; u < 4; ++u) {
            int row = srow + u * 32;
            cp16(aofs + (uint32_t)(row * 36 + skq) * 4, &A[(size_t)(m0 + row) * DIM + k0 + skq]);
            cp16(bofs + (uint32_t)(row * 36 + skq) * 4, &W[(size_t)(n0 + row) * DIM + k0 + skq]);
        }
        cp_commit();
    };

    float acc[4][4][4] = {};
    stage(0, 0);
    for (int kt = 0; kt < 24; ++kt) {
        if (kt + 1 < 24) { stage((kt + 1) & 1, (kt + 1) * 32); cp_wait<1>(); }
        else cp_wait<0>();
        __syncthreads();
        const uint32_t* As = sm + (kt & 1) * 4608;
        const uint32_t* Bs = sm + 9216 + (kt & 1) * 4608;
        compute_tiles<36, 4>(As, Bs, wm, wn, lane, acc);
        __syncthreads();
    }

#pragma unroll
    for (int mt = 0; mt < 4; ++mt) {
        int row = m0 + wm * 64 + mt * 16 + (lane >> 2);
        int b0i = row >> 10, t0 = row & 1023;
#pragma unroll
        for (int nt = 0; nt < 4; ++nt) {
            int col = n0 + wn * 32 + nt * 8 + ((lane & 3) << 1);
            int h = col >> 6, d = col & 63;
            float bx = bias[col], by = bias[col + 1];
            float2 lo = make_float2(round_tf(acc[mt][nt][0] + bx), round_tf(acc[mt][nt][1] + by));
            float2 hi = make_float2(round_tf(acc[mt][nt][2] + bx), round_tf(acc[mt][nt][3] + by));
            *(float2*)&out[((size_t)(b0i * NH + h) * NT + t0) * HD + d] = lo;
            *(float2*)&out[((size_t)(b0i * NH + h) * NT + t0 + 8) * HD + d] = hi;
        }
    }
}

// ---------------------------------------------------------------------------
// 2) S = exp(Q K^T * SCALE) + row-sum partials. grid (8, 8, 96).
// smem: Qs,Ks each 128*68 u32 -> 69632 B dynamic.
// ---------------------------------------------------------------------------
__global__ __launch_bounds__(256, 2) void s_exp_kernel(float* __restrict__ attn)
{
    extern __shared__ uint32_t sm[];
    __shared__ float redsum[4][128];
    const uint32_t sbase = (uint32_t)__cvta_generic_to_shared(sm);

    const int tid = threadIdx.x;
    const int lane = tid & 31;
    const int wid = tid >> 5;
    const int wm = wid >> 2, wn = wid & 3;
    const int bh = blockIdx.z;
    const int m0 = blockIdx.y * 128;
    const int n0 = blockIdx.x * 128;

    const float* Q = g_q + (size_t)bh * NT * HD;
    const float* K = g_k + (size_t)bh * NT * HD;

    // stage full 128x64 Q and K tiles
    {
        const uint32_t kofs = sbase + (uint32_t)(128 * 68) * 4;
#pragma unroll
        for (int u = 0; u < 8; ++u) {
            int idx = tid + u * 256;
            int row = idx >> 4;
            int kq = (idx & 15) << 2;
            cp16(sbase + (uint32_t)(row * 68 + kq) * 4, &Q[(size_t)(m0 + row) * HD + kq]);
            cp16(kofs + (uint32_t)(row * 68 + kq) * 4, &K[(size_t)(n0 + row) * HD + kq]);
        }
        cp_commit();
        cp_wait<0>();
        __syncthreads();
    }

    float acc[4][4][4] = {};
    compute_tiles<68, 8>(sm, sm + 128 * 68, wm, wn, lane, acc);

    float rsum[4][2] = {};
    float* ap = attn + (size_t)bh * NT * NT;
#pragma unroll
    for (int mt = 0; mt < 4; ++mt) {
        int row = m0 + wm * 64 + mt * 16 + (lane >> 2);
#pragma unroll
        for (int nt = 0; nt < 4; ++nt) {
            int col = n0 + wn * 32 + nt * 8 + ((lane & 3) << 1);
            float e0 = __expf(acc[mt][nt][0] * SCALE);
            float e1 = __expf(acc[mt][nt][1] * SCALE);
            float e2 = __expf(acc[mt][nt][2] * SCALE);
            float e3 = __expf(acc[mt][nt][3] * SCALE);
            *(float2*)&ap[(size_t)row * NT + col] = make_float2(e0, e1);
            *(float2*)&ap[(size_t)(row + 8) * NT + col] = make_float2(e2, e3);
            rsum[mt][0] += e0 + e1;
            rsum[mt][1] += e2 + e3;
        }
    }
#pragma unroll
    for (int off = 1; off < 4; off <<= 1)
#pragma unroll
        for (int mt = 0; mt < 4; ++mt) {
            rsum[mt][0] += __shfl_xor_sync(0xffffffffu, rsum[mt][0], off);
            rsum[mt][1] += __shfl_xor_sync(0xffffffffu, rsum[mt][1], off);
        }
    if ((lane & 3) == 0) {
#pragma unroll
        for (int mt = 0; mt < 4; ++mt) {
            int r = wm * 64 + mt * 16 + (lane >> 2);
            redsum[wn][r] = rsum[mt][0];
            redsum[wn][r + 8] = rsum[mt][1];
        }
    }
    __syncthreads();
    if (tid < 128) {
        float s = redsum[0][tid] + redsum[1][tid] + redsum[2][tid] + redsum[3][tid];
        g_psum[((size_t)bh * NT + m0 + tid) * 8 + blockIdx.x] = s;
    }
}

// ---------------------------------------------------------------------------
// 3) O = P V with in-place normalization. grid (8, 96).
// Block 128x64, warps 4x2, warp tile 32x32.
// smem: Ps0,Ps1 (128*36 each), Vs0,Vs1 (64*36 each) -> 55296 B dynamic.
// ---------------------------------------------------------------------------
__global__ __launch_bounds__(256, 2) void pv_kernel(float* __restrict__ attn)
{
    extern __shared__ uint32_t sm[];
    __shared__ float invs[128];
    const uint32_t sbase = (uint32_t)__cvta_generic_to_shared(sm);

    const int tid = threadIdx.x;
    const int lane = tid & 31;
    const int wid = tid >> 5;
    const int wm = wid >> 1, wn = wid & 1;
    const int m0 = blockIdx.x * 128;
    const int bh = blockIdx.y;

    for (int r = tid; r < 128; r += 256) {
        const float* pp = &g_psum[((size_t)bh * NT + m0 + r) * 8];
        invs[r] = 1.0f / (pp[0] + pp[1] + pp[2] + pp[3] + pp[4] + pp[5] + pp[6] + pp[7]);
    }
    __syncthreads();

    const int srow = tid >> 3;          // P staging row (+u*32)
    const int skq = (tid & 7) << 2;
    float myinv[4];
#pragma unroll
    for (int u = 0; u < 4; ++u) myinv[u] = invs[srow + u * 32];

    float* Pg = attn + (size_t)bh * NT * NT;
    const float* V = g_v + (size_t)bh * NT * HD;

    const int vd = tid & 63;            // V staging: d (+0), k = tid>>6 (+u*4)
    const int vk = tid >> 6;

    auto stageV = [&](int buf, int k0) {
        uint32_t vofs = sbase + (uint32_t)(9216 + buf * 2304) * 4;
#pragma unroll
        for (int u = 0; u < 8; ++u) {
            int k = vk + u * 4;
            cp4(vofs + (uint32_t)(vd * 36 + k) * 4, &V[(size_t)(k0 + k) * HD + vd]);
        }
        cp_commit();
    };

    float4 pf[4], pf2[4];
#pragma unroll
    for (int u = 0; u < 4; ++u)
        pf[u] = *(const float4*)&Pg[(size_t)(m0 + srow + u * 32) * NT + skq];
    stageV(0, 0);

    float acc[2][4][4] = {};
    for (int kt = 0; kt < 32; ++kt) {
        const int cur = kt & 1;
        // normalize current P regs, write back final attn, stage tf32 into Ps[cur]
        uint32_t* Pb = sm + cur * 4608;
#pragma unroll
        for (int u = 0; u < 4; ++u) {
            int row = srow + u * 32;
            float4 v = pf[u];
            v.x *= myinv[u]; v.y *= myinv[u]; v.z *= myinv[u]; v.w *= myinv[u];
            *(float4*)&Pg[(size_t)(m0 + row) * NT + kt * 32 + skq] = v;
            uint4 t;
            t.x = f2tf(v.x); t.y = f2tf(v.y); t.z = f2tf(v.z); t.w = f2tf(v.w);
            *(uint4*)&Pb[row * 36 + skq] = t;
        }
        if (kt + 1 < 32) {
            stageV((kt + 1) & 1, (kt + 1) * 32);
#pragma unroll
            for (int u = 0; u < 4; ++u)
                pf2[u] = *(const float4*)&Pg[(size_t)(m0 + srow + u * 32) * NT + (kt + 1) * 32 + skq];
            cp_wait<1>();
        } else {
            cp_wait<0>();
        }
        __syncthreads();

        const uint32_t* Ps = sm + cur * 4608;
        const uint32_t* Vs = sm + 9216 + cur * 2304;
#pragma unroll
        for (int ks = 0; ks < 4; ++ks) {
            const int col = ks * 8 + (lane & 3);
            uint32_t a[2][4], b[4][2];
#pragma unroll
            for (int mt = 0; mt < 2; ++mt) {
                int r = wm * 32 + mt * 16 + (lane >> 2);
                a[mt][0] = Ps[r * 36 + col];
                a[mt][1] = Ps[(r + 8) * 36 + col];
                a[mt][2] = Ps[r * 36 + col + 4];
                a[mt][3] = Ps[(r + 8) * 36 + col + 4];
            }
#pragma unroll
            for (int nt = 0; nt < 4; ++nt) {
                int n = wn * 32 + nt * 8 + (lane >> 2);
                b[nt][0] = Vs[n * 36 + col];
                b[nt][1] = Vs[n * 36 + col + 4];
            }
#pragma unroll
            for (int mt = 0; mt < 2; ++mt)
#pragma unroll
                for (int nt = 0; nt < 4; ++nt)
                    mma8(acc[mt][nt], a[mt][0], a[mt][1], a[mt][2], a[mt][3],
                         b[nt][0], b[nt][1]);
        }
        __syncthreads();
#pragma unroll
        for (int u = 0; u < 4; ++u) pf[u] = pf2[u];
    }

    const int b = bh / NH, h = bh % NH;
#pragma unroll
    for (int mt = 0; mt < 2; ++mt) {
        int row = m0 + wm * 32 + mt * 16 + (lane >> 2);
#pragma unroll
        for (int nt = 0; nt < 4; ++nt) {
            int d = wn * 32 + nt * 8 + ((lane & 3) << 1);
            *(float2*)&g_x[((size_t)b * NT + row) * DIM + h * HD + d] =
                make_float2(round_tf(acc[mt][nt][0]), round_tf(acc[mt][nt][1]));
            *(float2*)&g_x[((size_t)b * NT + row + 8) * DIM + h * HD + d] =
                make_float2(round_tf(acc[mt][nt][2]), round_tf(acc[mt][nt][3]));
        }
    }
}

// ---------------------------------------------------------------------------
// 4) output projection, cp.async double-buffered. grid (6, 64).
// ---------------------------------------------------------------------------
__global__ __launch_bounds__(256, 2) void proj_gemm_kernel(
    const float* __restrict__ bias, float* __restrict__ out)
{
    extern __shared__ uint32_t sm[];
    const uint32_t sbase = (uint32_t)__cvta_generic_to_shared(sm);

    const float* A = g_x;
    const float* W = g_w + (size_t)3 * DIM * DIM;

    const int tid = threadIdx.x;
    const int lane = tid & 31;
    const int wid = tid >> 5;
    const int wm = wid >> 2, wn = wid & 3;
    const int m0 = blockIdx.y * 128;
    const int n0 = blockIdx.x * 128;

    const int srow = tid >> 3;
    const int skq = (tid & 7) << 2;

    auto stage = [&](int buf, int k0) {
        uint32_t aofs = sbase + (uint32_t)(buf * 4608) * 4;
        uint32_t bofs = sbase + (uint32_t)(9216 + buf * 4608) * 4;
#pragma unroll
        for (int u = 0; u < 4; ++u) {
            int row = srow + u * 32;
            cp16(aofs + (uint32_t)(row * 36 + skq) * 4, &A[(size_t)(m0 + row) * DIM + k0 + skq]);
            cp16(bofs + (uint32_t)(row * 36 + skq) * 4, &W[(size_t)(n0 + row) * DIM + k0 + skq]);
        }
        cp_commit();
    };

    float acc[4][4][4] = {};
    stage(0, 0);
    for (int kt = 0; kt < 24; ++kt) {
        if (kt + 1 < 24) { stage((kt + 1) & 1, (kt + 1) * 32); cp_wait<1>(); }
        else cp_wait<0>();
        __syncthreads();
        const uint32_t* As = sm + (kt & 1) * 4608;
        const uint32_t* Bs = sm + 9216 + (kt & 1) * 4608;
        compute_tiles<36, 4>(As, Bs, wm, wn, lane, acc);
        __syncthreads();
    }

#pragma unroll
    for (int mt = 0; mt < 4; ++mt) {
        int row = m0 + wm * 64 + mt * 16 + (lane >> 2);
#pragma unroll
        for (int nt = 0; nt < 4; ++nt) {
            int col = n0 + wn * 32 + nt * 8 + ((lane & 3) << 1);
            float bx = bias[col], by = bias[col + 1];
            *(float2*)&out[(size_t)row * DIM + col] =
                make_float2(acc[mt][nt][0] + bx, acc[mt][nt][1] + by);
            *(float2*)&out[(size_t)(row + 8) * DIM + col] =
                make_float2(acc[mt][nt][2] + bx, acc[mt][nt][3] + by);
        }
    }
}

// ---------------------------------------------------------------------------

extern "C" void kernel_launch(void* const* d_in, const int* in_sizes, int n_in,
                              void* d_out, int out_size)
{
    const float* tfeat = (const float*)d_in[0];
    const float* wq = (const float*)d_in[1];
    const float* bq = (const float*)d_in[2];
    const float* wk = (const float*)d_in[3];
    const float* bk = (const float*)d_in[4];
    const float* wv = (const float*)d_in[5];
    const float* bv = (const float*)d_in[6];
    const float* wp = (const float*)d_in[7];
    const float* bp = (const float*)d_in[8];

    float* xout = (float*)d_out;
    float* attn_out = (float*)d_out + (size_t)BATCH * NT * DIM;

    float* gtf; cudaGetSymbolAddress((void**)&gtf, g_tf);
    float* gw;  cudaGetSymbolAddress((void**)&gw, g_w);

    const int WN4 = DIM * DIM / 4;
    round_kernel<<<(BATCH * NT * DIM / 4 + 255) / 256, 256>>>(tfeat, gtf, BATCH * NT * DIM / 4);
    round_kernel<<<(WN4 + 255) / 256, 256>>>(wq, gw + 0 * DIM * DIM, WN4);
    round_kernel<<<(WN4 + 255) / 256, 256>>>(wk, gw + 1 * DIM * DIM, WN4);
    round_kernel<<<(WN4 + 255) / 256, 256>>>(wv, gw + 2 * DIM * DIM, WN4);
    round_kernel<<<(WN4 + 255) / 256, 256>>>(wp, gw + 3 * DIM * DIM, WN4);

    cudaFuncSetAttribute(qkv_gemm_kernel, cudaFuncAttributeMaxDynamicSharedMemorySize, 73728);
    cudaFuncSetAttribute(s_exp_kernel, cudaFuncAttributeMaxDynamicSharedMemorySize, 69632);
    cudaFuncSetAttribute(pv_kernel, cudaFuncAttributeMaxDynamicSharedMemorySize, 55296);
    cudaFuncSetAttribute(proj_gemm_kernel, cudaFuncAttributeMaxDynamicSharedMemorySize, 73728);

    qkv_gemm_kernel<<<dim3(DIM / 128, (BATCH * NT) / 128, 3), 256, 73728>>>(bq, bk, bv);
    s_exp_kernel<<<dim3(NT / 128, NT / 128, NBH), 256, 69632>>>(attn_out);
    pv_kernel<<<dim3(NT / 128, NBH), 256, 55296>>>(attn_out);
    proj_gemm_kernel<<<dim3(DIM / 128, (BATCH * NT) / 128), 256, 73728>>>(bp, xout);
}